// round 1
// baseline (speedup 1.0000x reference)
#include <cuda_runtime.h>

#define NTOK  16384
#define DPROJ 1024

// Per-cluster token compaction scratch (allowed: __device__ globals, no mallocs).
__device__ int g_count[4];
__device__ int g_perm[4 * NTOK];

__global__ void k_zero() {
    if (threadIdx.x < 4) g_count[threadIdx.x] = 0;
}

__global__ void k_classify(const int* __restrict__ inp) {
    int t = blockIdx.x * 256 + threadIdx.x;
    if (t >= NTOK) return;
    int tok = inp[t];
    int c = (tok >= 200000) ? 3 : (tok >= 40000) ? 2 : (tok >= 20000) ? 1 : 0;
    int pos = atomicAdd(&g_count[c], 1);
    g_perm[c * NTOK + pos] = t;
}

// Tiled GEMM: C[m,n] = 32 * sum_k emb[row_m, k] * proj[nb+n, k]
// A = gathered emb rows [TM=64, D], B = proj [1024, D] (both K-contiguous).
// Block: 256 threads, 64x64 tile, TK=16, 4x4 register block per thread.
template <int D>
__global__ void __launch_bounds__(256)
k_gemm(const int* __restrict__ inp, const float* __restrict__ emb,
       const float* __restrict__ proj, float* __restrict__ out,
       int cluster, int lo)
{
    constexpr int TK = 16;
    __shared__ float As[TK][64];   // transposed: As[k][m]
    __shared__ float Bs[TK][64];   // transposed: Bs[k][n]
    __shared__ int   s_tok[64];    // flat token position (or -1)
    __shared__ int   s_row[64];    // emb row index (0 dummy when invalid)

    const int cnt = g_count[cluster];
    const int mt  = blockIdx.y;
    if (mt * 64 >= cnt) return;

    const int tid = threadIdx.x;
    const int nb  = blockIdx.x * 64;

    if (tid < 64) {
        int m = mt * 64 + tid;
        int t = -1, row = 0;
        if (m < cnt) { t = g_perm[cluster * NTOK + m]; row = inp[t] - lo; }
        s_tok[tid] = t;
        s_row[tid] = row;
    }
    __syncthreads();

    const int tx = tid & 15;   // n sub-tile: 16 threads x 4 outputs
    const int ty = tid >> 4;   // m sub-tile: 16 threads x 4 tokens

    // global-load mapping: each thread loads one float4 (row lm, k-quad lk)
    const int lm = tid >> 2;          // 0..63
    const int lk = (tid & 3) << 2;    // 0,4,8,12

    const float* embp  = emb  + (size_t)s_row[lm] * D + lk;
    const float* projp = proj + (size_t)(nb + lm) * D + lk;

    float acc[4][4] = {};

    for (int kb = 0; kb < D; kb += TK) {
        float4 va = *reinterpret_cast<const float4*>(embp  + kb);
        float4 vb = *reinterpret_cast<const float4*>(projp + kb);
        As[lk + 0][lm] = va.x; As[lk + 1][lm] = va.y;
        As[lk + 2][lm] = va.z; As[lk + 3][lm] = va.w;
        Bs[lk + 0][lm] = vb.x; Bs[lk + 1][lm] = vb.y;
        Bs[lk + 2][lm] = vb.z; Bs[lk + 3][lm] = vb.w;
        __syncthreads();

#pragma unroll
        for (int k = 0; k < TK; k++) {
            float4 a = *reinterpret_cast<const float4*>(&As[k][ty * 4]);
            float4 b = *reinterpret_cast<const float4*>(&Bs[k][tx * 4]);
            acc[0][0] += a.x * b.x; acc[0][1] += a.x * b.y;
            acc[0][2] += a.x * b.z; acc[0][3] += a.x * b.w;
            acc[1][0] += a.y * b.x; acc[1][1] += a.y * b.y;
            acc[1][2] += a.y * b.z; acc[1][3] += a.y * b.w;
            acc[2][0] += a.z * b.x; acc[2][1] += a.z * b.y;
            acc[2][2] += a.z * b.z; acc[2][3] += a.z * b.w;
            acc[3][0] += a.w * b.x; acc[3][1] += a.w * b.y;
            acc[3][2] += a.w * b.z; acc[3][3] += a.w * b.w;
        }
        __syncthreads();
    }

    const float SCALE = 32.0f;  // sqrt(1024)
#pragma unroll
    for (int i = 0; i < 4; i++) {
        int t = s_tok[ty * 4 + i];
        if (t >= 0) {
            float4 v = make_float4(acc[i][0] * SCALE, acc[i][1] * SCALE,
                                   acc[i][2] * SCALE, acc[i][3] * SCALE);
            *reinterpret_cast<float4*>(&out[(size_t)t * DPROJ + nb + tx * 4]) = v;
        }
    }
}

extern "C" void kernel_launch(void* const* d_in, const int* in_sizes, int n_in,
                              void* d_out, int out_size) {
    // metadata order: inp, emb0, proj0, emb1, proj1, emb2, proj2, emb3, proj3
    const int*   inp   = (const int*)d_in[0];
    const float* emb0  = (const float*)d_in[1];
    const float* proj0 = (const float*)d_in[2];
    const float* emb1  = (const float*)d_in[3];
    const float* proj1 = (const float*)d_in[4];
    const float* emb2  = (const float*)d_in[5];
    const float* proj2 = (const float*)d_in[6];
    const float* emb3  = (const float*)d_in[7];
    const float* proj3 = (const float*)d_in[8];
    float* out = (float*)d_out;

    k_zero<<<1, 32>>>();
    k_classify<<<NTOK / 256, 256>>>(inp);

    // grid.x = N tiles (1024/64 = 16), grid.y = max M tiles (16384/64 = 256);
    // blocks beyond the cluster's token count exit immediately.
    dim3 grid(16, 256);
    k_gemm<1024><<<grid, 256>>>(inp, emb0, proj0, out, 0, 0);
    k_gemm<256 ><<<grid, 256>>>(inp, emb1, proj1, out, 1, 20000);
    k_gemm<64  ><<<grid, 256>>>(inp, emb2, proj2, out, 2, 40000);
    k_gemm<16  ><<<grid, 256>>>(inp, emb3, proj3, out, 3, 200000);
}

// round 2
// speedup vs baseline: 2.2945x; 2.2945x over previous
#include <cuda_runtime.h>
#include <stdint.h>

#define NTOK  16384
#define DPROJ 1024
#define BM 128
#define BN 64
#define BK 32
#define MAX_MTILES 132   // sum over clusters of ceil(cnt/128) <= 128 + 3 + 1

__device__ int g_count[4];
__device__ int g_perm[4 * NTOK];

__global__ void k_zero() {
    if (threadIdx.x < 4) g_count[threadIdx.x] = 0;
}

__global__ void k_classify(const int* __restrict__ inp) {
    int t = blockIdx.x * 256 + threadIdx.x;
    int tok = inp[t];
    int c = (tok >= 200000) ? 3 : (tok >= 40000) ? 2 : (tok >= 20000) ? 1 : 0;
    int pos = atomicAdd(&g_count[c], 1);
    g_perm[c * NTOK + pos] = t;
}

__device__ __forceinline__ float tf32r(float x) {
    uint32_t u;
    asm("cvt.rna.tf32.f32 %0, %1;" : "=r"(u) : "f"(x));
    return __uint_as_float(u);
}

// Fused adaptive-embedding GEMM over all 4 clusters.
// C[m,n] = 32 * sum_k emb[row_m,k] * proj[n,k]   (tf32 MMA, fp32 accum)
__global__ void __launch_bounds__(256)
k_fused(const int* __restrict__ inp,
        const float* __restrict__ emb0, const float* __restrict__ proj0,
        const float* __restrict__ emb1, const float* __restrict__ proj1,
        const float* __restrict__ emb2, const float* __restrict__ proj2,
        const float* __restrict__ emb3, const float* __restrict__ proj3,
        float* __restrict__ out)
{
    __shared__ float As[BM][36];   // [m][k], pad 36 -> frag reads conflict-free
    __shared__ float Bs[BN][36];   // [n][k]
    __shared__ int   s_tok[BM];
    __shared__ int   s_row[BM];

    // ---- map blockIdx.y -> (cluster, mtile) via on-device prefix scan ----
    int y = blockIdx.y;
    int cluster = -1, mtile = 0, acc = 0;
#pragma unroll
    for (int c = 0; c < 4; c++) {
        int tiles = (g_count[c] + BM - 1) >> 7;
        if (cluster < 0 && y < acc + tiles) { cluster = c; mtile = y - acc; }
        acc += tiles;
    }
    if (cluster < 0) return;

    const float* emb;  const float* proj;  int D, lo;
    switch (cluster) {
        case 0:  emb = emb0; proj = proj0; D = 1024; lo = 0;      break;
        case 1:  emb = emb1; proj = proj1; D = 256;  lo = 20000;  break;
        case 2:  emb = emb2; proj = proj2; D = 64;   lo = 40000;  break;
        default: emb = emb3; proj = proj3; D = 16;   lo = 200000; break;
    }

    const int tid = threadIdx.x;
    const int cnt = g_count[cluster];

    if (tid < BM) {
        int m = mtile * BM + tid;
        int t = -1, row = 0;
        if (m < cnt) { t = g_perm[cluster * NTOK + m]; row = inp[t] - lo; }
        s_tok[tid] = t;
        s_row[tid] = row;
    }
    __syncthreads();

    // ---- global-load mapping: thread -> (rows ra+32j, k-quad qa) ----
    const int qa = tid & 7;     // k-quad within BK (qa*4 .. qa*4+3)
    const int ra = tid >> 3;    // base row
    const int nb = blockIdx.x * BN;

    const float* aptr[4];
#pragma unroll
    for (int j = 0; j < 4; j++)
        aptr[j] = emb + (size_t)s_row[ra + 32 * j] * D + qa * 4;
    const float* bptr[2];
#pragma unroll
    for (int j = 0; j < 2; j++)
        bptr[j] = proj + (size_t)(nb + ra + 32 * j) * D + qa * 4;

    // ---- warp / fragment mapping ----
    const int wid  = tid >> 5, lane = tid & 31;
    const int gid  = lane >> 2, tg = lane & 3;
    const int wm   = (wid >> 1) * 32;   // 4 warps along M
    const int wn   = (wid & 1) * 32;    // 2 warps along N

    float accum[2][4][4];
#pragma unroll
    for (int i = 0; i < 2; i++)
#pragma unroll
        for (int j = 0; j < 4; j++)
#pragma unroll
            for (int k = 0; k < 4; k++) accum[i][j][k] = 0.f;

    for (int kb = 0; kb < D; kb += BK) {
        const bool kok = (kb + qa * 4) < D;   // D multiple of 16 -> quad all-valid

        // A tile: 128 x 32, gathered rows, converted to tf32
#pragma unroll
        for (int j = 0; j < 4; j++) {
            float4 v = kok ? *(const float4*)(aptr[j] + kb)
                           : make_float4(0.f, 0.f, 0.f, 0.f);
            float4 w = make_float4(tf32r(v.x), tf32r(v.y), tf32r(v.z), tf32r(v.w));
            *(float4*)&As[ra + 32 * j][qa * 4] = w;
        }
        // B tile: 64 x 32
#pragma unroll
        for (int j = 0; j < 2; j++) {
            float4 v = kok ? *(const float4*)(bptr[j] + kb)
                           : make_float4(0.f, 0.f, 0.f, 0.f);
            float4 w = make_float4(tf32r(v.x), tf32r(v.y), tf32r(v.z), tf32r(v.w));
            *(float4*)&Bs[ra + 32 * j][qa * 4] = w;
        }
        __syncthreads();

#pragma unroll
        for (int ks = 0; ks < 4; ks++) {
            const int kk = ks * 8;
            uint32_t a[2][4], b[4][2];
#pragma unroll
            for (int mi = 0; mi < 2; mi++) {
                int m = wm + mi * 16 + gid;
                a[mi][0] = __float_as_uint(As[m    ][kk + tg    ]);
                a[mi][1] = __float_as_uint(As[m + 8][kk + tg    ]);
                a[mi][2] = __float_as_uint(As[m    ][kk + tg + 4]);
                a[mi][3] = __float_as_uint(As[m + 8][kk + tg + 4]);
            }
#pragma unroll
            for (int ni = 0; ni < 4; ni++) {
                int n = wn + ni * 8 + gid;
                b[ni][0] = __float_as_uint(Bs[n][kk + tg    ]);
                b[ni][1] = __float_as_uint(Bs[n][kk + tg + 4]);
            }
#pragma unroll
            for (int mi = 0; mi < 2; mi++)
#pragma unroll
                for (int ni = 0; ni < 4; ni++) {
                    asm volatile(
                        "mma.sync.aligned.m16n8k8.row.col.f32.tf32.tf32.f32 "
                        "{%0,%1,%2,%3}, {%4,%5,%6,%7}, {%8,%9}, {%0,%1,%2,%3};"
                        : "+f"(accum[mi][ni][0]), "+f"(accum[mi][ni][1]),
                          "+f"(accum[mi][ni][2]), "+f"(accum[mi][ni][3])
                        : "r"(a[mi][0]), "r"(a[mi][1]), "r"(a[mi][2]), "r"(a[mi][3]),
                          "r"(b[ni][0]), "r"(b[ni][1]));
                }
        }
        __syncthreads();
    }

    // ---- epilogue: scale by 32, scatter to out[token, :] ----
#pragma unroll
    for (int mi = 0; mi < 2; mi++) {
#pragma unroll
        for (int half = 0; half < 2; half++) {
            int rl = wm + mi * 16 + gid + half * 8;
            int t  = s_tok[rl];
            if (t >= 0) {
                float* op = out + (size_t)t * DPROJ + nb + wn;
#pragma unroll
                for (int ni = 0; ni < 4; ni++) {
                    float2 v;
                    v.x = accum[mi][ni][half * 2 + 0] * 32.f;
                    v.y = accum[mi][ni][half * 2 + 1] * 32.f;
                    *(float2*)(op + ni * 8 + tg * 2) = v;
                }
            }
        }
    }
}

extern "C" void kernel_launch(void* const* d_in, const int* in_sizes, int n_in,
                              void* d_out, int out_size) {
    const int*   inp   = (const int*)d_in[0];
    const float* emb0  = (const float*)d_in[1];
    const float* proj0 = (const float*)d_in[2];
    const float* emb1  = (const float*)d_in[3];
    const float* proj1 = (const float*)d_in[4];
    const float* emb2  = (const float*)d_in[5];
    const float* proj2 = (const float*)d_in[6];
    const float* emb3  = (const float*)d_in[7];
    const float* proj3 = (const float*)d_in[8];
    float* out = (float*)d_out;

    k_zero<<<1, 32>>>();
    k_classify<<<NTOK / 256, 256>>>(inp);

    dim3 grid(DPROJ / BN, MAX_MTILES);   // (16, 132)
    k_fused<<<grid, 256>>>(inp, emb0, proj0, emb1, proj1,
                           emb2, proj2, emb3, proj3, out);
}

// round 3
// speedup vs baseline: 3.2105x; 1.3992x over previous
#include <cuda_runtime.h>
#include <stdint.h>

#define NTOK  16384
#define DPROJ 1024
#define BM 128
#define BN 64
#define BK 32
#define ASTRIDE 36
#define MAX_MTILES 132   // sum over clusters of ceil(cnt/128) <= 131

__device__ int g_count[4];
__device__ int g_perm[4 * NTOK];

__global__ void k_classify(const int* __restrict__ inp) {
    int t = blockIdx.x * 256 + threadIdx.x;
    int tok = inp[t];
    int c = (tok >= 200000) ? 3 : (tok >= 40000) ? 2 : (tok >= 20000) ? 1 : 0;
    int pos = atomicAdd(&g_count[c], 1);
    g_perm[c * NTOK + pos] = t;
}

__device__ __forceinline__ float tf32r(float x) {
    uint32_t u;
    asm("cvt.rna.tf32.f32 %0, %1;" : "=r"(u) : "f"(x));
    return __uint_as_float(u);
}
__device__ __forceinline__ float4 tf32r4(float4 v) {
    return make_float4(tf32r(v.x), tf32r(v.y), tf32r(v.z), tf32r(v.w));
}

// Fused adaptive-embedding GEMM over all 4 clusters, 2-stage pipelined.
// C[m,n] = 32 * sum_k emb[row_m,k] * proj[n,k]   (tf32 MMA, fp32 accum)
__global__ void __launch_bounds__(256)
k_fused(const int* __restrict__ inp,
        const float* __restrict__ emb0, const float* __restrict__ proj0,
        const float* __restrict__ emb1, const float* __restrict__ proj1,
        const float* __restrict__ emb2, const float* __restrict__ proj2,
        const float* __restrict__ emb3, const float* __restrict__ proj3,
        float* __restrict__ out)
{
    extern __shared__ float smem[];
    float* As = smem;                                  // [2][BM][ASTRIDE]
    float* Bs = smem + 2 * BM * ASTRIDE;               // [2][BN][ASTRIDE]
    int* s_tok = (int*)(Bs + 2 * BN * ASTRIDE);        // [BM]
    int* s_row = s_tok + BM;                           // [BM]

    // ---- map blockIdx.y -> (cluster, mtile) ----
    int y = blockIdx.y;
    int cluster = -1, mtile = 0, acc = 0;
#pragma unroll
    for (int c = 0; c < 4; c++) {
        int tiles = (g_count[c] + BM - 1) >> 7;
        if (cluster < 0 && y < acc + tiles) { cluster = c; mtile = y - acc; }
        acc += tiles;
    }
    if (cluster < 0) return;

    const float* emb;  const float* proj;  int D, lo;
    switch (cluster) {
        case 0:  emb = emb0; proj = proj0; D = 1024; lo = 0;      break;
        case 1:  emb = emb1; proj = proj1; D = 256;  lo = 20000;  break;
        case 2:  emb = emb2; proj = proj2; D = 64;   lo = 40000;  break;
        default: emb = emb3; proj = proj3; D = 16;   lo = 200000; break;
    }

    const int tid = threadIdx.x;
    const int cnt = g_count[cluster];

    if (tid < BM) {
        int m = mtile * BM + tid;
        int t = -1, row = 0;
        if (m < cnt) { t = g_perm[cluster * NTOK + m]; row = inp[t] - lo; }
        s_tok[tid] = t;
        s_row[tid] = row;
    }
    __syncthreads();

    // ---- loader mapping: thread -> (rows ra+32j, k-quad qa) ----
    const int qa = tid & 7;
    const int ra = tid >> 3;
    const int nb = blockIdx.x * BN;

    const float* aptr[4];
#pragma unroll
    for (int j = 0; j < 4; j++)
        aptr[j] = emb + (size_t)s_row[ra + 32 * j] * D + qa * 4;
    const float* bptr[2];
#pragma unroll
    for (int j = 0; j < 2; j++)
        bptr[j] = proj + (size_t)(nb + ra + 32 * j) * D + qa * 4;

    // ---- warp / fragment mapping ----
    const int wid  = tid >> 5, lane = tid & 31;
    const int gid  = lane >> 2, tg = lane & 3;
    const int wm   = (wid >> 1) * 32;
    const int wn   = (wid & 1) * 32;

    float accum[2][4][4];
#pragma unroll
    for (int i = 0; i < 2; i++)
#pragma unroll
        for (int j = 0; j < 4; j++)
#pragma unroll
            for (int k = 0; k < 4; k++) accum[i][j][k] = 0.f;

    const float4 fz = make_float4(0.f, 0.f, 0.f, 0.f);
    float4 pa[4], pb[2];

    // prologue: fetch k-block 0, fill stage 0
    {
        bool kok = (qa * 4) < D;
#pragma unroll
        for (int j = 0; j < 4; j++) pa[j] = kok ? *(const float4*)(aptr[j]) : fz;
#pragma unroll
        for (int j = 0; j < 2; j++) pb[j] = kok ? *(const float4*)(bptr[j]) : fz;
#pragma unroll
        for (int j = 0; j < 4; j++)
            *(float4*)&As[(ra + 32 * j) * ASTRIDE + qa * 4] = tf32r4(pa[j]);
#pragma unroll
        for (int j = 0; j < 2; j++)
            *(float4*)&Bs[(ra + 32 * j) * ASTRIDE + qa * 4] = tf32r4(pb[j]);
    }
    __syncthreads();

    int buf = 0;
    for (int kb = 0; kb < D; kb += BK) {
        const int nkb = kb + BK;
        const bool have_next = nkb < D;

        // prefetch next k-block into registers (overlaps with MMA below)
        if (have_next) {
            bool kok = (nkb + qa * 4) < D;
#pragma unroll
            for (int j = 0; j < 4; j++) pa[j] = kok ? *(const float4*)(aptr[j] + nkb) : fz;
#pragma unroll
            for (int j = 0; j < 2; j++) pb[j] = kok ? *(const float4*)(bptr[j] + nkb) : fz;
        }

        const float* Ab = As + buf * BM * ASTRIDE;
        const float* Bb = Bs + buf * BN * ASTRIDE;

#pragma unroll
        for (int ks = 0; ks < 4; ks++) {
            const int kk = ks * 8;
            uint32_t a[2][4], b[4][2];
#pragma unroll
            for (int mi = 0; mi < 2; mi++) {
                int m = wm + mi * 16 + gid;
                a[mi][0] = __float_as_uint(Ab[(m    ) * ASTRIDE + kk + tg    ]);
                a[mi][1] = __float_as_uint(Ab[(m + 8) * ASTRIDE + kk + tg    ]);
                a[mi][2] = __float_as_uint(Ab[(m    ) * ASTRIDE + kk + tg + 4]);
                a[mi][3] = __float_as_uint(Ab[(m + 8) * ASTRIDE + kk + tg + 4]);
            }
#pragma unroll
            for (int ni = 0; ni < 4; ni++) {
                int n = wn + ni * 8 + gid;
                b[ni][0] = __float_as_uint(Bb[n * ASTRIDE + kk + tg    ]);
                b[ni][1] = __float_as_uint(Bb[n * ASTRIDE + kk + tg + 4]);
            }
#pragma unroll
            for (int mi = 0; mi < 2; mi++)
#pragma unroll
                for (int ni = 0; ni < 4; ni++) {
                    asm volatile(
                        "mma.sync.aligned.m16n8k8.row.col.f32.tf32.tf32.f32 "
                        "{%0,%1,%2,%3}, {%4,%5,%6,%7}, {%8,%9}, {%0,%1,%2,%3};"
                        : "+f"(accum[mi][ni][0]), "+f"(accum[mi][ni][1]),
                          "+f"(accum[mi][ni][2]), "+f"(accum[mi][ni][3])
                        : "r"(a[mi][0]), "r"(a[mi][1]), "r"(a[mi][2]), "r"(a[mi][3]),
                          "r"(b[ni][0]), "r"(b[ni][1]));
                }
        }

        // stage next k-block into the other buffer
        if (have_next) {
            float* An = As + (buf ^ 1) * BM * ASTRIDE;
            float* Bn = Bs + (buf ^ 1) * BN * ASTRIDE;
#pragma unroll
            for (int j = 0; j < 4; j++)
                *(float4*)&An[(ra + 32 * j) * ASTRIDE + qa * 4] = tf32r4(pa[j]);
#pragma unroll
            for (int j = 0; j < 2; j++)
                *(float4*)&Bn[(ra + 32 * j) * ASTRIDE + qa * 4] = tf32r4(pb[j]);
        }
        __syncthreads();
        buf ^= 1;
    }

    // ---- epilogue: scale by 32, scatter to out[token, :] ----
#pragma unroll
    for (int mi = 0; mi < 2; mi++) {
#pragma unroll
        for (int half = 0; half < 2; half++) {
            int rl = wm + mi * 16 + gid + half * 8;
            int t  = s_tok[rl];
            if (t >= 0) {
                float* op = out + (size_t)t * DPROJ + nb + wn;
#pragma unroll
                for (int ni = 0; ni < 4; ni++) {
                    float2 v;
                    v.x = accum[mi][ni][half * 2 + 0] * 32.f;
                    v.y = accum[mi][ni][half * 2 + 1] * 32.f;
                    *(float2*)(op + ni * 8 + tg * 2) = v;
                }
            }
        }
    }
}

extern "C" void kernel_launch(void* const* d_in, const int* in_sizes, int n_in,
                              void* d_out, int out_size) {
    const int*   inp   = (const int*)d_in[0];
    const float* emb0  = (const float*)d_in[1];
    const float* proj0 = (const float*)d_in[2];
    const float* emb1  = (const float*)d_in[3];
    const float* proj1 = (const float*)d_in[4];
    const float* emb2  = (const float*)d_in[5];
    const float* proj2 = (const float*)d_in[6];
    const float* emb3  = (const float*)d_in[7];
    const float* proj3 = (const float*)d_in[8];
    float* out = (float*)d_out;

    const int smem_bytes = (2 * BM * ASTRIDE + 2 * BN * ASTRIDE) * 4 + 2 * BM * 4;
    cudaFuncSetAttribute(k_fused, cudaFuncAttributeMaxDynamicSharedMemorySize,
                         smem_bytes);

    void* gcnt = nullptr;
    cudaGetSymbolAddress(&gcnt, g_count);
    cudaMemsetAsync(gcnt, 0, 4 * sizeof(int));

    k_classify<<<NTOK / 256, 256>>>(inp);

    dim3 grid(DPROJ / BN, MAX_MTILES);   // (16, 132)
    k_fused<<<grid, 256, smem_bytes>>>(inp, emb0, proj0, emb1, proj1,
                                       emb2, proj2, emb3, proj3, out);
}